// round 16
// baseline (speedup 1.0000x reference)
#include <cuda_runtime.h>

#define T25   25
#define HID   100
#define G4    400
#define RT    832             // 26 warps: warps 0-12 = kh0, 13-25 = kh1

typedef unsigned long long u64;

__device__ float g_h1 [(size_t)512 * T25 * HID];  // layer1 hidden states
__device__ float g_z2x[(size_t)512 * T25 * G4];   // layer2 input projection

union U4 { float4 f4; ulonglong2 u2; };
union U2 { float2 f2; u64 u; };

__device__ __forceinline__ u64 pk(float lo, float hi) {
    u64 r; asm("mov.b64 %0, {%1,%2};" : "=l"(r) : "f"(lo), "f"(hi)); return r;
}
__device__ __forceinline__ void ffma2(u64& d, u64 a, u64 b) {
    asm("fma.rn.f32x2 %0, %1, %2, %0;" : "+l"(d) : "l"(a), "l"(b));
}
__device__ __forceinline__ float hsum(u64 v) {
    float a, b; asm("mov.b64 {%0,%1}, %2;" : "=f"(a), "=f"(b) : "l"(v)); return a + b;
}
__device__ __forceinline__ float sigm(float x)   { return 1.0f / (1.0f + __expf(-x)); }
__device__ __forceinline__ float mytanh(float x) { float e = __expf(-2.0f * x); return (1.0f - e) / (1.0f + e); }

#define BAR_ARRIVE(id) asm volatile("bar.arrive %0, %1;" :: "r"(id), "r"(RT) : "memory")
#define BAR_SYNCN(id)  asm volatile("bar.sync %0, %1;"   :: "r"(id), "r"(RT) : "memory")

// ============================================================================
// Shared helpers (compile-time bounds — spill-free, proven R14)
// ============================================================================
template<int NQ>
__device__ __forceinline__ void inproj_compute(
    const float (*xs)[104], const float* __restrict__ wsm,
    int c, int rb, float bv, u64* acc)
{
    u64 binit = pk(bv, bv);
    #pragma unroll
    for (int p = 0; p < 2 * NQ; p++) acc[p] = binit;

    #pragma unroll 2
    for (int k = 0; k < HID; k++) {
        float w = wsm[k * G4 + c];
        u64 wd = pk(w, w);
        const float* xr = &xs[k][rb];
        #pragma unroll
        for (int q = 0; q < NQ; q++) {
            U4 x; x.f4 = *(const float4*)(xr + 4 * q);
            ffma2(acc[2 * q],     x.u2.x, wd);
            ffma2(acc[2 * q + 1], x.u2.y, wd);
        }
    }
}

template<int NQ>
__device__ __forceinline__ void store_smem(
    float* __restrict__ dst, const u64* acc, int c, int rb)
{
    float* p0 = dst + rb * G4 + c;
    #pragma unroll
    for (int p = 0; p < 2 * NQ; p++) {
        U2 v; v.u = acc[p];
        p0[(2 * p    ) * G4] = v.f2.x;
        p0[(2 * p + 1) * G4] = v.f2.y;
    }
}

// ============================================================================
// Kernel 1 (A+B): emb gather -> inproj1 (smem z1) -> rec layer1 -> h1 global
// (R14 fused<true>, measured ~99us)
// ============================================================================
#define AB_OFF_WZ   0          // k1x during prologue, z1 after
#define AB_OFF_XS   40000      // x transposed [100][104] (prologue), reused:
#define AB_OFF_HS   40000      //   hs [4][104]
#define AB_OFF_ZP   40416      //   zp2 float2 [4][400]
#define AB_SMEM_FLOATS 50400
#define AB_SMEM_BYTES  (AB_SMEM_FLOATS * 4)   // 201600

__global__ void __launch_bounds__(RT, 1) ab_kernel(
    const int*   __restrict__ feats,  // [12800]
    const float* __restrict__ emb,    // [VOCAB][100]
    const float* __restrict__ k1,     // [200][400]
    const float* __restrict__ b1,     // [400]
    float*       __restrict__ h_out)  // [12800][100]
{
    extern __shared__ __align__(16) float sm[];
    float* wz = sm + AB_OFF_WZ;
    float (*xs)[104]   = (float(*)[104])(sm + AB_OFF_XS);
    float (*hs)[104]   = (float(*)[104])(sm + AB_OFF_HS);
    float2 (*zp2)[G4]  = (float2(*)[G4])(sm + AB_OFF_ZP);

    const int tid  = threadIdx.x;
    const int b0   = blockIdx.x * 4;
    const int row0 = b0 * T25;

    // ---- stage k1x ----
    for (int i4 = tid; i4 < HID * G4 / 4; i4 += RT)
        ((float4*)wz)[i4] = ((const float4*)k1)[i4];

    // ---- gather x transposed (MLP-batched) ----
    {
        float4 v[4];
        int    jj[4], rr[4];
        bool   mm[4];
        const float* base[4];
        #pragma unroll
        for (int i = 0; i < 4; i++) {
            int idx = tid + i * RT;
            mm[i] = (idx < 2500);
            jj[i] = idx / 100;
            rr[i] = idx % 100;
        }
        #pragma unroll
        for (int i = 0; i < 4; i++)
            if (mm[i]) base[i] = emb + (long long)__ldg(feats + row0 + rr[i]) * HID;
        #pragma unroll
        for (int i = 0; i < 4; i++)
            if (mm[i]) v[i] = *(const float4*)(base[i] + 4 * jj[i]);
        #pragma unroll
        for (int i = 0; i < 4; i++) {
            if (mm[i]) {
                xs[4 * jj[i] + 0][rr[i]] = v[i].x;
                xs[4 * jj[i] + 1][rr[i]] = v[i].y;
                xs[4 * jj[i] + 2][rr[i]] = v[i].z;
                xs[4 * jj[i] + 3][rr[i]] = v[i].w;
            }
        }
    }
    __syncthreads();

    // ---- prologue GEMM z1 = x @ k1x + b1 (registers) ----
    u64 zacc[26];
    const int pc = tid % G4;
    const int rg = tid / G4;
    if (rg == 0)      inproj_compute<13>(xs, wz, pc, 0,  __ldg(b1 + pc), zacc);
    else if (rg == 1) inproj_compute<12>(xs, wz, pc, 52, __ldg(b1 + pc), zacc);
    __syncthreads();

    // ---- store z1 over k1x; init hs; load recurrent weights ----
    if (rg == 0)      store_smem<13>(wz, zacc, pc, 0);
    else if (rg == 1) store_smem<12>(wz, zacc, pc, 52);
    for (int i = tid; i < 4 * 104; i += RT) ((float*)hs)[i] = 0.f;

    const int wid = tid >> 5;
    const int kh  = (wid >= 13);
    const int c   = tid - (kh ? 416 : 0);
    const bool act = (c < G4);
    const int gr = c / 100;
    const int gu = c % 100;

    const float* Wh = k1 + HID * G4;
    u64 wp[26];
    #pragma unroll
    for (int j = 0; j < 26; j++) {
        int k = kh * 52 + 2 * j;
        float w0 = (act && k     < HID) ? __ldg(Wh + (k    ) * G4 + c) : 0.f;
        float w1 = (act && k + 1 < HID) ? __ldg(Wh + (k + 1) * G4 + c) : 0.f;
        wp[j] = pk(w0, w1);
    }
    __syncthreads();

    // ---- recurrence: z1 read from smem, split barriers ----
    float cst = 0.f;
    for (int t = 0; t < T25; t++) {
        if (act) {
            u64 a0 = 0ULL, a1 = 0ULL, a2 = 0ULL, a3 = 0ULL;
            if (kh == 0) {
                #pragma unroll
                for (int j4 = 0; j4 < 13; j4++) {
                    U4 v0; v0.f4 = *(const float4*)&hs[0][4 * j4];
                    U4 v1; v1.f4 = *(const float4*)&hs[1][4 * j4];
                    U4 v2; v2.f4 = *(const float4*)&hs[2][4 * j4];
                    U4 v3; v3.f4 = *(const float4*)&hs[3][4 * j4];
                    ffma2(a0, v0.u2.x, wp[2 * j4]); ffma2(a0, v0.u2.y, wp[2 * j4 + 1]);
                    ffma2(a1, v1.u2.x, wp[2 * j4]); ffma2(a1, v1.u2.y, wp[2 * j4 + 1]);
                    ffma2(a2, v2.u2.x, wp[2 * j4]); ffma2(a2, v2.u2.y, wp[2 * j4 + 1]);
                    ffma2(a3, v3.u2.x, wp[2 * j4]); ffma2(a3, v3.u2.y, wp[2 * j4 + 1]);
                }
            } else {
                #pragma unroll
                for (int j4 = 0; j4 < 12; j4++) {
                    U4 v0; v0.f4 = *(const float4*)&hs[0][52 + 4 * j4];
                    U4 v1; v1.f4 = *(const float4*)&hs[1][52 + 4 * j4];
                    U4 v2; v2.f4 = *(const float4*)&hs[2][52 + 4 * j4];
                    U4 v3; v3.f4 = *(const float4*)&hs[3][52 + 4 * j4];
                    ffma2(a0, v0.u2.x, wp[2 * j4]); ffma2(a0, v0.u2.y, wp[2 * j4 + 1]);
                    ffma2(a1, v1.u2.x, wp[2 * j4]); ffma2(a1, v1.u2.y, wp[2 * j4 + 1]);
                    ffma2(a2, v2.u2.x, wp[2 * j4]); ffma2(a2, v2.u2.y, wp[2 * j4 + 1]);
                    ffma2(a3, v3.u2.x, wp[2 * j4]); ffma2(a3, v3.u2.y, wp[2 * j4 + 1]);
                }
            }
            float* zpf = (float*)&zp2[0][0] + 2 * c + kh;
            zpf[0 * G4 * 2] = hsum(a0);
            zpf[1 * G4 * 2] = hsum(a1);
            zpf[2 * G4 * 2] = hsum(a2);
            zpf[3 * G4 * 2] = hsum(a3);
        }

        if (kh) {
            BAR_ARRIVE(1);
            BAR_SYNCN(2);
        } else {
            BAR_SYNCN(1);
            if (act) {
                const float* zrow = wz + (gr * T25 + t) * G4;
                float2 p0 = zp2[gr][gu];
                float2 p1 = zp2[gr][gu + 100];
                float2 p2 = zp2[gr][gu + 200];
                float2 p3 = zp2[gr][gu + 300];
                float zi = zrow[gu]       + p0.x + p0.y;
                float zj = zrow[gu + 100] + p1.x + p1.y;
                float zf = zrow[gu + 200] + p2.x + p2.y;
                float zo = zrow[gu + 300] + p3.x + p3.y;
                cst = cst * sigm(zf + 1.0f) + sigm(zi) * mytanh(zj);
                float hn = mytanh(cst) * sigm(zo);
                hs[gr][gu] = hn;
                h_out[((long long)(b0 + gr) * T25 + t) * HID + gu] = hn;
            }
            BAR_SYNCN(2);
        }
    }
}

// ============================================================================
// Kernel 2 (C): z2x = h1 @ k2x + b2  (R12 inproj, measured ~28us)
// ============================================================================
#define IP_SMEM_B ((HID * G4 + HID * 104) * 4)   // 201600 bytes

template<int NQ>
__device__ __forceinline__ void inproj_store_gmem(
    float* __restrict__ out, const u64* acc, int c, int rb, int row0)
{
    #pragma unroll
    for (int p = 0; p < 2 * NQ; p++) {
        U2 v; v.u = acc[p];
        out[(long long)(row0 + rb + 2 * p) * G4 + c]     = v.f2.x;
        out[(long long)(row0 + rb + 2 * p + 1) * G4 + c] = v.f2.y;
    }
}

__global__ void __launch_bounds__(800, 1) inproj_kernel(
    const float* __restrict__ src,    // [12800][100] (h1)
    const float* __restrict__ W,      // k2x [100][400]
    const float* __restrict__ bias,   // [400]
    float*       __restrict__ out)    // [12800][400]
{
    extern __shared__ __align__(16) float smp[];
    float* wsm = smp;
    float (*xs)[104] = (float(*)[104])(smp + HID * G4);

    const int tid  = threadIdx.x;
    const int row0 = blockIdx.x * 100;

    for (int i4 = tid; i4 < HID * G4 / 4; i4 += 800)
        ((float4*)wsm)[i4] = ((const float4*)W)[i4];

    {
        float4 v[4];
        int    jj[4], rr[4];
        bool   mm[4];
        #pragma unroll
        for (int i = 0; i < 4; i++) {
            int idx = tid + i * 800;
            mm[i] = (idx < 2500);
            jj[i] = idx / 100;
            rr[i] = idx % 100;
        }
        #pragma unroll
        for (int i = 0; i < 4; i++)
            if (mm[i]) v[i] = *(const float4*)(src + (long long)(row0 + rr[i]) * HID + 4 * jj[i]);
        #pragma unroll
        for (int i = 0; i < 4; i++) {
            if (mm[i]) {
                xs[4 * jj[i] + 0][rr[i]] = v[i].x;
                xs[4 * jj[i] + 1][rr[i]] = v[i].y;
                xs[4 * jj[i] + 2][rr[i]] = v[i].z;
                xs[4 * jj[i] + 3][rr[i]] = v[i].w;
            }
        }
    }
    __syncthreads();

    u64 zacc[26];
    const int c  = tid % G4;
    const int rg = tid / G4;
    const float bv = __ldg(bias + c);
    if (rg == 0) {
        inproj_compute<13>(xs, wsm, c, 0,  bv, zacc);
        inproj_store_gmem<13>(out, zacc, c, 0, row0);
    } else {
        inproj_compute<12>(xs, wsm, c, 52, bv, zacc);
        inproj_store_gmem<12>(out, zacc, c, 52, row0);
    }
}

// ============================================================================
// Kernel 3 (D): layer-2 recurrence + FC head (R15 rec2, measured ~76us)
// ============================================================================
__global__ void __launch_bounds__(RT, 1) rec2_kernel(
    const float* __restrict__ zin,    // [12800][400] = g_z2x
    const float* __restrict__ Wh,     // k2[100:200][400]
    const float* __restrict__ wfc1, const float* __restrict__ bfc1,
    const float* __restrict__ wfc2, const float* __restrict__ bfc2,
    float*       __restrict__ out)    // [512][2]
{
    __shared__ __align__(16) float  hs[4][104];
    __shared__ __align__(16) float2 zp2[4][G4];
    __shared__ float zsm[2][4][G4];
    __shared__ float fc1s[4][128];

    const int tid = threadIdx.x;
    const int b0  = blockIdx.x * 4;
    const int wid = tid >> 5;
    const int kh  = (wid >= 13);
    const int c   = tid - (kh ? 416 : 0);
    const bool act = (c < G4);
    const int gr = c / 100;
    const int gu = c % 100;

    u64 wp[26];
    #pragma unroll
    for (int j = 0; j < 26; j++) {
        int k = kh * 52 + 2 * j;
        float w0 = (act && k     < HID) ? __ldg(Wh + (k    ) * G4 + c) : 0.f;
        float w1 = (act && k + 1 < HID) ? __ldg(Wh + (k + 1) * G4 + c) : 0.f;
        wp[j] = pk(w0, w1);
    }
    for (int i = tid; i < 4 * 104; i += RT) ((float*)hs)[i] = 0.f;

    if (kh && act) {
        const float* zr = zin + ((long long)(b0 + gr) * T25 + 0) * G4 + gu;
        zsm[0][0][c] = __ldg(zr);
        zsm[0][1][c] = __ldg(zr + 100);
        zsm[0][2][c] = __ldg(zr + 200);
        zsm[0][3][c] = __ldg(zr + 300);
    }
    __syncthreads();

    float cst = 0.f;
    for (int t = 0; t < T25; t++) {
        if (act) {
            u64 a0 = 0ULL, a1 = 0ULL, a2 = 0ULL, a3 = 0ULL;
            if (kh == 0) {
                #pragma unroll
                for (int j4 = 0; j4 < 13; j4++) {
                    U4 v0; v0.f4 = *(const float4*)&hs[0][4 * j4];
                    U4 v1; v1.f4 = *(const float4*)&hs[1][4 * j4];
                    U4 v2; v2.f4 = *(const float4*)&hs[2][4 * j4];
                    U4 v3; v3.f4 = *(const float4*)&hs[3][4 * j4];
                    ffma2(a0, v0.u2.x, wp[2 * j4]); ffma2(a0, v0.u2.y, wp[2 * j4 + 1]);
                    ffma2(a1, v1.u2.x, wp[2 * j4]); ffma2(a1, v1.u2.y, wp[2 * j4 + 1]);
                    ffma2(a2, v2.u2.x, wp[2 * j4]); ffma2(a2, v2.u2.y, wp[2 * j4 + 1]);
                    ffma2(a3, v3.u2.x, wp[2 * j4]); ffma2(a3, v3.u2.y, wp[2 * j4 + 1]);
                }
            } else {
                #pragma unroll
                for (int j4 = 0; j4 < 12; j4++) {
                    U4 v0; v0.f4 = *(const float4*)&hs[0][52 + 4 * j4];
                    U4 v1; v1.f4 = *(const float4*)&hs[1][52 + 4 * j4];
                    U4 v2; v2.f4 = *(const float4*)&hs[2][52 + 4 * j4];
                    U4 v3; v3.f4 = *(const float4*)&hs[3][52 + 4 * j4];
                    ffma2(a0, v0.u2.x, wp[2 * j4]); ffma2(a0, v0.u2.y, wp[2 * j4 + 1]);
                    ffma2(a1, v1.u2.x, wp[2 * j4]); ffma2(a1, v1.u2.y, wp[2 * j4 + 1]);
                    ffma2(a2, v2.u2.x, wp[2 * j4]); ffma2(a2, v2.u2.y, wp[2 * j4 + 1]);
                    ffma2(a3, v3.u2.x, wp[2 * j4]); ffma2(a3, v3.u2.y, wp[2 * j4 + 1]);
                }
            }
            float* zpf = (float*)&zp2[0][0] + 2 * c + kh;
            zpf[0 * G4 * 2] = hsum(a0);
            zpf[1 * G4 * 2] = hsum(a1);
            zpf[2 * G4 * 2] = hsum(a2);
            zpf[3 * G4 * 2] = hsum(a3);
        }

        if (kh) {
            BAR_ARRIVE(1);
            if (act && t + 1 < T25) {
                const float* zr = zin + ((long long)(b0 + gr) * T25 + (t + 1)) * G4 + gu;
                const int nb = (t + 1) & 1;
                zsm[nb][0][c] = __ldg(zr);
                zsm[nb][1][c] = __ldg(zr + 100);
                zsm[nb][2][c] = __ldg(zr + 200);
                zsm[nb][3][c] = __ldg(zr + 300);
            }
            BAR_SYNCN(2);
        } else {
            BAR_SYNCN(1);
            if (act) {
                const int bf = t & 1;
                float2 p0 = zp2[gr][gu];
                float2 p1 = zp2[gr][gu + 100];
                float2 p2 = zp2[gr][gu + 200];
                float2 p3 = zp2[gr][gu + 300];
                float zi = zsm[bf][0][c] + p0.x + p0.y;
                float zj = zsm[bf][1][c] + p1.x + p1.y;
                float zf = zsm[bf][2][c] + p2.x + p2.y;
                float zo = zsm[bf][3][c] + p3.x + p3.y;
                cst = cst * sigm(zf + 1.0f) + sigm(zi) * mytanh(zj);
                float hn = mytanh(cst) * sigm(zo);
                hs[gr][gu] = hn;
            }
            BAR_SYNCN(2);
        }
    }

    __syncthreads();
    for (int idx = tid; idx < 4 * 128; idx += RT) {
        int r = idx / 128, j = idx % 128;
        float a = bfc1[j];
        #pragma unroll 4
        for (int k = 0; k < HID; k++)
            a += hs[r][k] * __ldg(wfc1 + k * 128 + j);
        fc1s[r][j] = a;
    }
    __syncthreads();
    if (tid < 8) {
        int r = tid / 2, cc = tid % 2;
        float a = bfc2[cc];
        #pragma unroll 8
        for (int k = 0; k < 128; k++)
            a += fc1s[r][k] * __ldg(wfc2 + k * 2 + cc);
        out[(b0 + r) * 2 + cc] = a;
    }
}

// ---------------------------------------------------------------------------
extern "C" void kernel_launch(void* const* d_in, const int* in_sizes, int n_in,
                              void* d_out, int out_size)
{
    const int*   feats = (const int*)  d_in[0];
    const float* emb   = (const float*)d_in[1];
    const float* k1    = (const float*)d_in[2];
    const float* b1    = (const float*)d_in[3];
    const float* k2    = (const float*)d_in[4];
    const float* b2    = (const float*)d_in[5];
    const float* wfc1  = (const float*)d_in[6];
    const float* bfc1  = (const float*)d_in[7];
    const float* wfc2  = (const float*)d_in[8];
    const float* bfc2  = (const float*)d_in[9];
    float* out = (float*)d_out;

    float *h1, *z2x;
    cudaGetSymbolAddress((void**)&h1,  g_h1);
    cudaGetSymbolAddress((void**)&z2x, g_z2x);

    cudaFuncSetAttribute(ab_kernel,
                         cudaFuncAttributeMaxDynamicSharedMemorySize, AB_SMEM_BYTES);
    cudaFuncSetAttribute(inproj_kernel,
                         cudaFuncAttributeMaxDynamicSharedMemorySize, IP_SMEM_B);

    // A+B: gather + inproj1 + rec1 -> h1
    ab_kernel<<<128, RT, AB_SMEM_BYTES>>>(feats, emb, k1, b1, h1);
    // C: z2x = h1 @ k2x + b2
    inproj_kernel<<<128, 800, IP_SMEM_B>>>(h1, k2, b2, z2x);
    // D: rec2 + FC head -> out
    rec2_kernel<<<128, RT>>>(z2x, k2 + HID * G4, wfc1, bfc1, wfc2, bfc2, out);
}

// round 17
// speedup vs baseline: 1.0781x; 1.0781x over previous
#include <cuda_runtime.h>

#define T25   25
#define HID   100
#define G4    400
#define RT    832             // 26 warps: warps 0-12 = kh0, 13-25 = kh1
#define IPROWS 87             // rows per inproj block
#define IPNB   148            // inproj blocks (fills all SMs)

typedef unsigned long long u64;

__device__ float g_h1 [(size_t)512 * T25 * HID];  // layer1 hidden states
__device__ float g_z2x[(size_t)512 * T25 * G4];   // layer2 input projection

union U4 { float4 f4; ulonglong2 u2; };
union U2 { float2 f2; u64 u; };

__device__ __forceinline__ u64 pk(float lo, float hi) {
    u64 r; asm("mov.b64 %0, {%1,%2};" : "=l"(r) : "f"(lo), "f"(hi)); return r;
}
__device__ __forceinline__ void ffma2(u64& d, u64 a, u64 b) {
    asm("fma.rn.f32x2 %0, %1, %2, %0;" : "+l"(d) : "l"(a), "l"(b));
}
__device__ __forceinline__ float hsum(u64 v) {
    float a, b; asm("mov.b64 {%0,%1}, %2;" : "=f"(a), "=f"(b) : "l"(v)); return a + b;
}
__device__ __forceinline__ float sigm(float x)   { return 1.0f / (1.0f + __expf(-x)); }
__device__ __forceinline__ float mytanh(float x) { float e = __expf(-2.0f * x); return (1.0f - e) / (1.0f + e); }

#define BAR_ARRIVE(id) asm volatile("bar.arrive %0, %1;" :: "r"(id), "r"(RT) : "memory")
#define BAR_SYNCN(id)  asm volatile("bar.sync %0, %1;"   :: "r"(id), "r"(RT) : "memory")

// ============================================================================
// Input-projection GEMM: 148 blocks x 87 rows x 400 cols, 800 threads.
// W staged in smem; x transposed in smem; FFMA2 row-pairs; masked stores.
// ============================================================================
#define XROW 88   // xs row dimension (rows 0..87 addressable)
#define IP_SMEM_B ((HID * G4 + HID * XROW) * 4)   // 195200 bytes

template<int NQ>
__device__ __forceinline__ void inproj_compute(
    const float (*xs)[XROW], const float* __restrict__ wsm,
    int c, int rb, float bv, u64* acc)
{
    u64 binit = pk(bv, bv);
    #pragma unroll
    for (int p = 0; p < 2 * NQ; p++) acc[p] = binit;

    #pragma unroll 2
    for (int k = 0; k < HID; k++) {
        float w = wsm[k * G4 + c];
        u64 wd = pk(w, w);
        const float* xr = &xs[k][rb];
        #pragma unroll
        for (int q = 0; q < NQ; q++) {
            U4 x; x.f4 = *(const float4*)(xr + 4 * q);
            ffma2(acc[2 * q],     x.u2.x, wd);
            ffma2(acc[2 * q + 1], x.u2.y, wd);
        }
    }
}

template<int NQ>
__device__ __forceinline__ void store_gmem_masked(
    float* __restrict__ out, const u64* acc, int c, int rb, int row0, int nrows)
{
    #pragma unroll
    for (int p = 0; p < 2 * NQ; p++) {
        U2 v; v.u = acc[p];
        int r0 = rb + 2 * p;
        if (r0 < nrows)     out[(long long)(row0 + r0)     * G4 + c] = v.f2.x;
        if (r0 + 1 < nrows) out[(long long)(row0 + r0 + 1) * G4 + c] = v.f2.y;
    }
}

__global__ void __launch_bounds__(800, 1) inproj_kernel(
    const float* __restrict__ src,    // [12800][100] or null (then gather emb)
    const int*   __restrict__ feats,  // [12800] or null
    const float* __restrict__ emb,    // [VOCAB][100]
    const float* __restrict__ W,      // [100][400]
    const float* __restrict__ bias,   // [400]
    float*       __restrict__ out)    // [12800][400]
{
    extern __shared__ __align__(16) float smp[];
    float* wsm = smp;
    float (*xs)[XROW] = (float(*)[XROW])(smp + HID * G4);

    const int tid   = threadIdx.x;
    const int row0  = blockIdx.x * IPROWS;
    const int nrows = min(IPROWS, 12800 - row0);

    // stage W
    for (int i4 = tid; i4 < HID * G4 / 4; i4 += 800)
        ((float4*)wsm)[i4] = ((const float4*)W)[i4];

    // stage x transposed, batched loads (MLP >= 3): 25*87 = 2175 tasks
    {
        float4 v[3];
        int    jj[3], rr[3];
        bool   mm[3];
        const float* base[3];
        #pragma unroll
        for (int i = 0; i < 3; i++) {
            int idx = tid + i * 800;
            jj[i] = idx / IPROWS;
            rr[i] = idx % IPROWS;
            mm[i] = (idx < 25 * IPROWS) && (rr[i] < nrows);
        }
        #pragma unroll
        for (int i = 0; i < 3; i++) {
            if (mm[i]) {
                base[i] = feats
                    ? emb + (long long)__ldg(feats + row0 + rr[i]) * HID
                    : src + (long long)(row0 + rr[i]) * HID;
            }
        }
        #pragma unroll
        for (int i = 0; i < 3; i++)
            if (mm[i]) v[i] = *(const float4*)(base[i] + 4 * jj[i]);
        #pragma unroll
        for (int i = 0; i < 3; i++) {
            if (mm[i]) {
                xs[4 * jj[i] + 0][rr[i]] = v[i].x;
                xs[4 * jj[i] + 1][rr[i]] = v[i].y;
                xs[4 * jj[i] + 2][rr[i]] = v[i].z;
                xs[4 * jj[i] + 3][rr[i]] = v[i].w;
            }
        }
    }
    __syncthreads();

    // GEMM: rg0 rows 0..43, rg1 rows 44..87 (row 87 masked; max valid 86)
    u64 zacc[22];
    const int c  = tid % G4;
    const int rg = tid / G4;
    const float bv = __ldg(bias + c);
    if (rg == 0) {
        inproj_compute<11>(xs, wsm, c, 0, bv, zacc);
        store_gmem_masked<11>(out, zacc, c, 0, row0, nrows);
    } else {
        inproj_compute<11>(xs, wsm, c, 44, bv, zacc);
        store_gmem_masked<11>(out, zacc, c, 44, row0, nrows);
    }
}

// ============================================================================
// Recurrence core (R12-proven): 128 blocks x 4 rows, 832 threads, split
// barriers, zsm double-buffered zin staging by kh1 during gate phase.
// HOUT: store h1; FC: run FC head at the end.
// ============================================================================
template<bool HOUT, bool FC>
__global__ void __launch_bounds__(RT, 1) rec_kernel(
    const float* __restrict__ zin,    // [12800][400]
    const float* __restrict__ Wh,     // [100][400]
    float*       __restrict__ h_out,  // [12800][100] (HOUT)
    const float* __restrict__ wfc1, const float* __restrict__ bfc1,
    const float* __restrict__ wfc2, const float* __restrict__ bfc2,
    float*       __restrict__ out)    // [512][2] (FC)
{
    __shared__ __align__(16) float  hs[4][104];
    __shared__ __align__(16) float2 zp2[4][G4];
    __shared__ float zsm[2][4][G4];
    __shared__ float fc1s[4][128];

    const int tid = threadIdx.x;
    const int b0  = blockIdx.x * 4;
    const int wid = tid >> 5;
    const int kh  = (wid >= 13);
    const int c   = tid - (kh ? 416 : 0);
    const bool act = (c < G4);
    const int gr = c / 100;
    const int gu = c % 100;

    u64 wp[26];
    #pragma unroll
    for (int j = 0; j < 26; j++) {
        int k = kh * 52 + 2 * j;
        float w0 = (act && k     < HID) ? __ldg(Wh + (k    ) * G4 + c) : 0.f;
        float w1 = (act && k + 1 < HID) ? __ldg(Wh + (k + 1) * G4 + c) : 0.f;
        wp[j] = pk(w0, w1);
    }
    for (int i = tid; i < 4 * 104; i += RT) ((float*)hs)[i] = 0.f;

    if (kh && act) {
        const float* zr = zin + ((long long)(b0 + gr) * T25 + 0) * G4 + gu;
        zsm[0][0][c] = __ldg(zr);
        zsm[0][1][c] = __ldg(zr + 100);
        zsm[0][2][c] = __ldg(zr + 200);
        zsm[0][3][c] = __ldg(zr + 300);
    }
    __syncthreads();

    float cst = 0.f;
    for (int t = 0; t < T25; t++) {
        if (act) {
            u64 a0 = 0ULL, a1 = 0ULL, a2 = 0ULL, a3 = 0ULL;
            if (kh == 0) {
                #pragma unroll
                for (int j4 = 0; j4 < 13; j4++) {
                    U4 v0; v0.f4 = *(const float4*)&hs[0][4 * j4];
                    U4 v1; v1.f4 = *(const float4*)&hs[1][4 * j4];
                    U4 v2; v2.f4 = *(const float4*)&hs[2][4 * j4];
                    U4 v3; v3.f4 = *(const float4*)&hs[3][4 * j4];
                    ffma2(a0, v0.u2.x, wp[2 * j4]); ffma2(a0, v0.u2.y, wp[2 * j4 + 1]);
                    ffma2(a1, v1.u2.x, wp[2 * j4]); ffma2(a1, v1.u2.y, wp[2 * j4 + 1]);
                    ffma2(a2, v2.u2.x, wp[2 * j4]); ffma2(a2, v2.u2.y, wp[2 * j4 + 1]);
                    ffma2(a3, v3.u2.x, wp[2 * j4]); ffma2(a3, v3.u2.y, wp[2 * j4 + 1]);
                }
            } else {
                #pragma unroll
                for (int j4 = 0; j4 < 12; j4++) {
                    U4 v0; v0.f4 = *(const float4*)&hs[0][52 + 4 * j4];
                    U4 v1; v1.f4 = *(const float4*)&hs[1][52 + 4 * j4];
                    U4 v2; v2.f4 = *(const float4*)&hs[2][52 + 4 * j4];
                    U4 v3; v3.f4 = *(const float4*)&hs[3][52 + 4 * j4];
                    ffma2(a0, v0.u2.x, wp[2 * j4]); ffma2(a0, v0.u2.y, wp[2 * j4 + 1]);
                    ffma2(a1, v1.u2.x, wp[2 * j4]); ffma2(a1, v1.u2.y, wp[2 * j4 + 1]);
                    ffma2(a2, v2.u2.x, wp[2 * j4]); ffma2(a2, v2.u2.y, wp[2 * j4 + 1]);
                    ffma2(a3, v3.u2.x, wp[2 * j4]); ffma2(a3, v3.u2.y, wp[2 * j4 + 1]);
                }
            }
            float* zpf = (float*)&zp2[0][0] + 2 * c + kh;
            zpf[0 * G4 * 2] = hsum(a0);
            zpf[1 * G4 * 2] = hsum(a1);
            zpf[2 * G4 * 2] = hsum(a2);
            zpf[3 * G4 * 2] = hsum(a3);
        }

        if (kh) {
            BAR_ARRIVE(1);
            if (act && t + 1 < T25) {
                const float* zr = zin + ((long long)(b0 + gr) * T25 + (t + 1)) * G4 + gu;
                const int nb = (t + 1) & 1;
                zsm[nb][0][c] = __ldg(zr);
                zsm[nb][1][c] = __ldg(zr + 100);
                zsm[nb][2][c] = __ldg(zr + 200);
                zsm[nb][3][c] = __ldg(zr + 300);
            }
            BAR_SYNCN(2);
        } else {
            BAR_SYNCN(1);
            if (act) {
                const int bf = t & 1;
                float2 p0 = zp2[gr][gu];
                float2 p1 = zp2[gr][gu + 100];
                float2 p2 = zp2[gr][gu + 200];
                float2 p3 = zp2[gr][gu + 300];
                float zi = zsm[bf][0][c] + p0.x + p0.y;
                float zj = zsm[bf][1][c] + p1.x + p1.y;
                float zf = zsm[bf][2][c] + p2.x + p2.y;
                float zo = zsm[bf][3][c] + p3.x + p3.y;
                cst = cst * sigm(zf + 1.0f) + sigm(zi) * mytanh(zj);
                float hn = mytanh(cst) * sigm(zo);
                hs[gr][gu] = hn;
                if (HOUT)
                    h_out[((long long)(b0 + gr) * T25 + t) * HID + gu] = hn;
            }
            BAR_SYNCN(2);
        }
    }

    if (FC) {
        __syncthreads();
        for (int idx = tid; idx < 4 * 128; idx += RT) {
            int r = idx / 128, j = idx % 128;
            float a = bfc1[j];
            #pragma unroll 4
            for (int k = 0; k < HID; k++)
                a += hs[r][k] * __ldg(wfc1 + k * 128 + j);
            fc1s[r][j] = a;
        }
        __syncthreads();
        if (tid < 8) {
            int r = tid / 2, cc = tid % 2;
            float a = bfc2[cc];
            #pragma unroll 8
            for (int k = 0; k < 128; k++)
                a += fc1s[r][k] * __ldg(wfc2 + k * 2 + cc);
            out[(b0 + r) * 2 + cc] = a;
        }
    }
}

// ---------------------------------------------------------------------------
extern "C" void kernel_launch(void* const* d_in, const int* in_sizes, int n_in,
                              void* d_out, int out_size)
{
    const int*   feats = (const int*)  d_in[0];
    const float* emb   = (const float*)d_in[1];
    const float* k1    = (const float*)d_in[2];
    const float* b1    = (const float*)d_in[3];
    const float* k2    = (const float*)d_in[4];
    const float* b2    = (const float*)d_in[5];
    const float* wfc1  = (const float*)d_in[6];
    const float* bfc1  = (const float*)d_in[7];
    const float* wfc2  = (const float*)d_in[8];
    const float* bfc2  = (const float*)d_in[9];
    float* out = (float*)d_out;

    float *h1, *z2x;
    cudaGetSymbolAddress((void**)&h1,  g_h1);
    cudaGetSymbolAddress((void**)&z2x, g_z2x);

    cudaFuncSetAttribute(inproj_kernel,
                         cudaFuncAttributeMaxDynamicSharedMemorySize, IP_SMEM_B);

    // A: zx1 -> reuse g_z2x buffer first for layer1 projection
    inproj_kernel<<<IPNB, 800, IP_SMEM_B>>>(nullptr, feats, emb, k1, b1, z2x);
    // B: layer-1 recurrence -> h1
    rec_kernel<true, false><<<128, RT>>>(z2x, k1 + HID * G4, h1,
                                         nullptr, nullptr, nullptr, nullptr, nullptr);
    // C: z2x = h1 @ k2x + b2
    inproj_kernel<<<IPNB, 800, IP_SMEM_B>>>(h1, nullptr, nullptr, k2, b2, z2x);
    // D: layer-2 recurrence + FC head -> out
    rec_kernel<false, true><<<128, RT>>>(z2x, k2 + HID * G4, nullptr,
                                         wfc1, bfc1, wfc2, bfc2, out);
}